// round 14
// baseline (speedup 1.0000x reference)
#include <cuda_runtime.h>
#include <cstdint>

#define HH 56
#define WW 56
#define HM 50
#define WM 50
#define NPLANES 16384            // 64 * 256
#define COUNT_M 51380224ull      // 64*256*56*56
#define NSLOTS 512

// Scratch (allocation-free). g_partial is zero at load; k_finalize resets it
// after reading, so every graph replay sees zeros again.
__device__ unsigned g_partial[NSLOTS];
__device__ float g_scale;
__device__ unsigned long long g_dmask[NPLANES * HH];   // 7.34 MB packed dilated mask

// One CTA (128 thr) per plane. Front-batched streaming loads (MLP=5), 20-bit
// compare mask guarding the rare shift/atomic work. Dilation: since the
// horizontal dilate H distributes over OR, each output row vertical-ORs the
// RAW seed rows [o-6,o] and applies H once (OR of shifts 0..6 == the pad=6
// reduce_window). Only 2 barriers total.
__global__ __launch_bounds__(128) void k_pass1(const float* __restrict__ u,
                                               const float* __restrict__ gamma) {
    __shared__ unsigned long long row[HM];   // raw seed bitmask rows
    const int plane = blockIdx.x;
    const int tid = threadIdx.x;
    const float g = __ldg(gamma);

    // 625 float4 per plane; 5 batched loads per thread, 5th fed +inf when OOB
    // (inf < g never fires, so its nibble is 0 -> no predicate in the loop).
    const float4* u4 = (const float4*)(u + (size_t)plane * (HM * WM));
    float4 v[5];
    #pragma unroll
    for (int k = 0; k < 4; ++k) v[k] = __ldcs(u4 + tid + k * 128);
    const float finf = __int_as_float(0x7f800000);
    v[4] = make_float4(finf, finf, finf, finf);
    if (tid < 625 - 512) v[4] = __ldcs(u4 + tid + 512);

    if (tid < HM) row[tid] = 0ull;

    // Precompute (row, col) per chunk — independent of loads, fills the wait.
    int rr[5], cc[5];
    #pragma unroll
    for (int k = 0; k < 5; ++k) {
        const int e = (tid + k * 128) * 4;
        rr[k] = e / WM;
        cc[k] = e - rr[k] * WM;
    }
    __syncthreads();   // row[] zeroed

    unsigned bits = 0;
    #pragma unroll
    for (int k = 0; k < 5; ++k) {
        bits |= ( (unsigned)(v[k].x < g)
                | ((unsigned)(v[k].y < g) << 1)
                | ((unsigned)(v[k].z < g) << 2)
                | ((unsigned)(v[k].w < g) << 3) ) << (k * 4);
    }
    if (bits) {                                    // rare per lane (~33%)
        #pragma unroll
        for (int k = 0; k < 5; ++k) {
            const unsigned nib = (bits >> (k * 4)) & 0xFu;
            if (nib) {
                const unsigned long long m = (unsigned long long)nib << cc[k];
                const unsigned long long lo = m & ((1ull << WM) - 1ull);
                const unsigned long long hi = m >> WM;
                if (lo) atomicOr(&row[rr[k]], lo);
                if (hi) atomicOr(&row[rr[k] + 1], hi);   // cc in {47,48,49}; rr+1<=49
            }
        }
    }
    __syncthreads();

    // Fused dilation: s = OR of raw seed rows [max(0,o-6)..min(o,49)], then
    // one horizontal dilate (H commutes with OR). Store + popcount.
    unsigned v1 = 0;
    if (tid < HH) {
        int lo = tid - 6; if (lo < 0) lo = 0;
        int hi = (tid < HM) ? tid : (HM - 1);
        unsigned long long s = 0ull;
        #pragma unroll 1
        for (int r = lo; r <= hi; ++r) s |= row[r];
        unsigned long long t1 = s  | (s  << 1);
        unsigned long long t2 = t1 | (t1 << 2);
        unsigned long long d  = t2 | (t2 << 3);      // shifts 0..6, bits stay < 56
        g_dmask[(size_t)plane * HH + tid] = d;
        v1 = (unsigned)__popcll(d);
    }
    // Warps 0 and 1 hold all nonzero v1 (tid<56). Reduce in-warp, RED per warp.
    if (tid < 64) {
        #pragma unroll
        for (int off = 16; off; off >>= 1) v1 += __shfl_down_sync(0xffffffffu, v1, off);
        if ((tid & 31) == 0)
            atomicAdd(&g_partial[plane & (NSLOTS - 1)], v1);   // spread slots
    }
}

// One block: sum the 512 slots, compute scale (f32, like the jnp reference),
// reset slots for the next replay.
__global__ __launch_bounds__(NSLOTS) void k_finalize() {
    __shared__ unsigned s[NSLOTS / 32];
    const int tid = threadIdx.x;
    unsigned v = g_partial[tid];
    g_partial[tid] = 0u;
    #pragma unroll
    for (int off = 16; off; off >>= 1) v += __shfl_down_sync(0xffffffffu, v, off);
    if ((tid & 31) == 0) s[tid >> 5] = v;
    __syncthreads();
    if (tid < 32) {
        unsigned w = (tid < NSLOTS / 32) ? s[tid] : 0u;
        #pragma unroll
        for (int off = 8; off; off >>= 1) w += __shfl_down_sync(0xffffffffu, w, off);
        if (tid == 0)
            g_scale = (float)COUNT_M / (float)(COUNT_M - (unsigned long long)w);
    }
}

// Elementwise apply, 2x float4 per thread, streaming loads/stores (measured
// best config: 78% DRAM).
__global__ __launch_bounds__(256) void k_pass2(const float* __restrict__ x,
                                               float* __restrict__ out) {
    const unsigned i40 = blockIdx.x * 512u + threadIdx.x;
    const unsigned i41 = i40 + 256u;
    const float s = g_scale;

    const unsigned p0 = i40 / 784u, r0q = i40 - p0 * 784u;
    const unsigned row0 = r0q / 14u, w40 = r0q - row0 * 14u;
    const unsigned p1 = i41 / 784u, r1q = i41 - p1 * 784u;
    const unsigned row1 = r1q / 14u, w41 = r1q - row1 * 14u;

    const unsigned long long d0 = __ldg(&g_dmask[p0 * HH + row0]);
    const unsigned long long d1 = __ldg(&g_dmask[p1 * HH + row1]);
    const float4 x0 = __ldcs(((const float4*)x) + i40);
    const float4 x1 = __ldcs(((const float4*)x) + i41);

    const unsigned n0 = (unsigned)(d0 >> (w40 * 4u)) & 0xFu;
    const unsigned n1 = (unsigned)(d1 >> (w41 * 4u)) & 0xFu;
    float4 o0, o1;
    o0.x = (n0 & 1u) ? 0.f : x0.x * s;
    o0.y = (n0 & 2u) ? 0.f : x0.y * s;
    o0.z = (n0 & 4u) ? 0.f : x0.z * s;
    o0.w = (n0 & 8u) ? 0.f : x0.w * s;
    o1.x = (n1 & 1u) ? 0.f : x1.x * s;
    o1.y = (n1 & 2u) ? 0.f : x1.y * s;
    o1.z = (n1 & 4u) ? 0.f : x1.z * s;
    o1.w = (n1 & 8u) ? 0.f : x1.w * s;
    __stcs(((float4*)out) + i40, o0);
    __stcs(((float4*)out) + i41, o1);
}

extern "C" void kernel_launch(void* const* d_in, const int* in_sizes, int n_in,
                              void* d_out, int out_size) {
    const float* x     = (const float*)d_in[0];
    const float* u     = (const float*)d_in[1];
    const float* gamma = (const float*)d_in[2];
    float* out = (float*)d_out;

    k_pass1<<<NPLANES, 128>>>(u, gamma);
    k_finalize<<<1, NSLOTS>>>();
    k_pass2<<<(unsigned)(COUNT_M / 4ull / 512ull), 256>>>(x, out);   // 25088 blocks
}

// round 15
// speedup vs baseline: 1.0152x; 1.0152x over previous
#include <cuda_runtime.h>
#include <cstdint>

#define HH 56
#define WW 56
#define HM 50
#define WM 50
#define NPLANES 16384            // 64 * 256
#define COUNT_M 51380224ull      // 64*256*56*56
#define NSLOTS 256

// Scratch (allocation-free). g_partial is zero at load; k_reset (after pass2)
// zeros it again so every graph replay sees zeros.
__device__ unsigned g_partial[NSLOTS];
__device__ unsigned long long g_dmask[NPLANES * HH];   // 7.34 MB packed dilated mask

// One CTA (128 thr) per plane. Front-batched streaming loads (MLP=5), 20-bit
// compare mask guarding the rare shift/atomic work. Dilation: H (horizontal
// dilate) distributes over OR, so each output row vertical-ORs the RAW seed
// rows [o-6,o] and applies H once (OR of shifts 0..6 == the pad=6
// reduce_window). 2 barriers total.
__global__ __launch_bounds__(128) void k_pass1(const float* __restrict__ u,
                                               const float* __restrict__ gamma) {
    __shared__ unsigned long long row[HM];   // raw seed bitmask rows
    const int plane = blockIdx.x;
    const int tid = threadIdx.x;
    const float g = __ldg(gamma);

    // 625 float4 per plane; 5 batched loads per thread, 5th fed +inf when OOB
    // (inf < g never fires, so its nibble is 0 -> no predicate in the loop).
    const float4* u4 = (const float4*)(u + (size_t)plane * (HM * WM));
    float4 v[5];
    #pragma unroll
    for (int k = 0; k < 4; ++k) v[k] = __ldcs(u4 + tid + k * 128);
    const float finf = __int_as_float(0x7f800000);
    v[4] = make_float4(finf, finf, finf, finf);
    if (tid < 625 - 512) v[4] = __ldcs(u4 + tid + 512);

    if (tid < HM) row[tid] = 0ull;

    // Precompute (row, col) per chunk — independent of loads, fills the wait.
    int rr[5], cc[5];
    #pragma unroll
    for (int k = 0; k < 5; ++k) {
        const int e = (tid + k * 128) * 4;
        rr[k] = e / WM;
        cc[k] = e - rr[k] * WM;
    }
    __syncthreads();   // row[] zeroed

    unsigned bits = 0;
    #pragma unroll
    for (int k = 0; k < 5; ++k) {
        bits |= ( (unsigned)(v[k].x < g)
                | ((unsigned)(v[k].y < g) << 1)
                | ((unsigned)(v[k].z < g) << 2)
                | ((unsigned)(v[k].w < g) << 3) ) << (k * 4);
    }
    if (bits) {                                    // rare per lane (~33%)
        #pragma unroll
        for (int k = 0; k < 5; ++k) {
            const unsigned nib = (bits >> (k * 4)) & 0xFu;
            if (nib) {
                const unsigned long long m = (unsigned long long)nib << cc[k];
                const unsigned long long lo = m & ((1ull << WM) - 1ull);
                const unsigned long long hi = m >> WM;
                if (lo) atomicOr(&row[rr[k]], lo);
                if (hi) atomicOr(&row[rr[k] + 1], hi);   // cc in {47,48,49}; rr+1<=49
            }
        }
    }
    __syncthreads();

    // Fused dilation: s = OR of raw seed rows [max(0,o-6)..min(o,49)], then
    // one horizontal dilate. Store packed row + popcount.
    unsigned v1 = 0;
    if (tid < HH) {
        int lo = tid - 6; if (lo < 0) lo = 0;
        int hi = (tid < HM) ? tid : (HM - 1);
        unsigned long long s = 0ull;
        #pragma unroll 1
        for (int r = lo; r <= hi; ++r) s |= row[r];
        unsigned long long t1 = s  | (s  << 1);
        unsigned long long t2 = t1 | (t1 << 2);
        unsigned long long d  = t2 | (t2 << 3);      // shifts 0..6, bits stay < 56
        g_dmask[(size_t)plane * HH + tid] = d;
        v1 = (unsigned)__popcll(d);
    }
    // Warps 0 and 1 hold all nonzero v1 (tid<56). Reduce in-warp, RED per warp.
    if (tid < 64) {
        #pragma unroll
        for (int off = 16; off; off >>= 1) v1 += __shfl_down_sync(0xffffffffu, v1, off);
        if ((tid & 31) == 0)
            atomicAdd(&g_partial[plane & (NSLOTS - 1)], v1);   // spread slots
    }
}

// Elementwise apply, 2x float4 per thread. Each CTA derives the global scale
// itself from the 256 partial slots (L2-hot); the slot loads are issued after
// the streaming x loads so their latency hides under the memory window.
__global__ __launch_bounds__(256) void k_pass2(const float* __restrict__ x,
                                               float* __restrict__ out) {
    __shared__ unsigned sred[8];
    __shared__ float sscale;
    const unsigned tid = threadIdx.x;
    const unsigned i40 = blockIdx.x * 512u + tid;
    const unsigned i41 = i40 + 256u;

    const unsigned p0 = i40 / 784u, r0q = i40 - p0 * 784u;
    const unsigned row0 = r0q / 14u, w40 = r0q - row0 * 14u;
    const unsigned p1 = i41 / 784u, r1q = i41 - p1 * 784u;
    const unsigned row1 = r1q / 14u, w41 = r1q - row1 * 14u;

    // Issue all global loads up front (max MLP), including the slot load.
    const unsigned long long d0 = __ldg(&g_dmask[p0 * HH + row0]);
    const unsigned long long d1 = __ldg(&g_dmask[p1 * HH + row1]);
    const float4 x0 = __ldcs(((const float4*)x) + i40);
    const float4 x1 = __ldcs(((const float4*)x) + i41);
    unsigned v = __ldg(&g_partial[tid]);           // NSLOTS == blockDim.x

    // Block-reduce the 256 partials -> scale (identical in every CTA).
    #pragma unroll
    for (int off = 16; off; off >>= 1) v += __shfl_down_sync(0xffffffffu, v, off);
    if ((tid & 31u) == 0u) sred[tid >> 5] = v;
    __syncthreads();
    if (tid < 32u) {
        unsigned w = (tid < 8u) ? sred[tid] : 0u;
        #pragma unroll
        for (int off = 4; off; off >>= 1) w += __shfl_down_sync(0xffffffffu, w, off);
        if (tid == 0u)
            sscale = (float)COUNT_M / (float)(COUNT_M - (unsigned long long)w);
    }
    __syncthreads();
    const float s = sscale;

    const unsigned n0 = (unsigned)(d0 >> (w40 * 4u)) & 0xFu;
    const unsigned n1 = (unsigned)(d1 >> (w41 * 4u)) & 0xFu;
    float4 o0, o1;
    o0.x = (n0 & 1u) ? 0.f : x0.x * s;
    o0.y = (n0 & 2u) ? 0.f : x0.y * s;
    o0.z = (n0 & 4u) ? 0.f : x0.z * s;
    o0.w = (n0 & 8u) ? 0.f : x0.w * s;
    o1.x = (n1 & 1u) ? 0.f : x1.x * s;
    o1.y = (n1 & 2u) ? 0.f : x1.y * s;
    o1.z = (n1 & 4u) ? 0.f : x1.z * s;
    o1.w = (n1 & 8u) ? 0.f : x1.w * s;
    __stcs(((float4*)out) + i40, o0);
    __stcs(((float4*)out) + i41, o1);
}

// After pass2: zero the slots so the next graph replay starts clean.
__global__ __launch_bounds__(NSLOTS) void k_reset() {
    g_partial[threadIdx.x] = 0u;
}

extern "C" void kernel_launch(void* const* d_in, const int* in_sizes, int n_in,
                              void* d_out, int out_size) {
    const float* x     = (const float*)d_in[0];
    const float* u     = (const float*)d_in[1];
    const float* gamma = (const float*)d_in[2];
    float* out = (float*)d_out;

    k_pass1<<<NPLANES, 128>>>(u, gamma);
    k_pass2<<<(unsigned)(COUNT_M / 4ull / 512ull), 256>>>(x, out);   // 25088 blocks
    k_reset<<<1, NSLOTS>>>();
}